// round 1
// baseline (speedup 1.0000x reference)
#include <cuda_runtime.h>
#include <math.h>

// Problem dims
#define kB   32
#define kW   256
#define kIN  4096
#define kH   1024
#define kZ   100
#define kG   3072          // 3*kH
#define kDH  1124          // kZ + kH
#define OUT_CHUNK 819200   // kB*kW*kZ

// -------------------- device scratch (no runtime allocs allowed) --------------------
__device__ float g_gi[kW * kB * kG];        // ~100.7 MB: precomputed input gates
__device__ float g_hbuf[2][kB * kH];
__device__ float g_zbuf[kB * kZ];
__device__ float g_dense[kB * kZ];
__device__ float g_zpre[kB * kZ];
__device__ unsigned long long g_bar_all = 0ULL;
__device__ unsigned long long g_bar_head = 0ULL;

// Monotonic-counter barrier: self-consistent across graph replays (no reset needed).
// Counter starts at a multiple of G at every launch because every launch adds an
// exact multiple of G. 64-bit => no wraparound concerns.
__device__ __forceinline__ void dev_barrier(unsigned long long* ctr, unsigned G)
{
    __syncthreads();
    if (threadIdx.x == 0) {
        __threadfence();
        unsigned long long old = atomicAdd(ctr, 1ULL);
        unsigned long long tgt = old - (old % (unsigned long long)G) + (unsigned long long)G;
        volatile unsigned long long* v = (volatile unsigned long long*)ctr;
        while (*v < tgt) { }
        __threadfence();
    }
    __syncthreads();
}

__device__ __forceinline__ float sigmoidf_(float x) { return 1.0f / (1.0f + expf(-x)); }
__device__ __forceinline__ float softplusf_(float x)
{
    // logaddexp(x, 0) = max(x,0) + log1p(exp(-|x|))  (matches jax.nn.softplus)
    return fmaxf(x, 0.0f) + log1pf(expf(-fabsf(x)));
}

// ==================================================================================
// Kernel 1: gi[w][b][g] = sum_f x[b][w][f] * W_ih[g][f] + b_ih[g]
// Classic fp32 SGEMM: M=8192 (m=b*256+w), N=3072, K=4096. 128x128x8 tile, 8x8/thread.
// ==================================================================================
__global__ void __launch_bounds__(256) gemm_gi_kernel(
    const float* __restrict__ x, const float* __restrict__ Wih,
    const float* __restrict__ bih)
{
    __shared__ float As[8][132];
    __shared__ float Bs[8][132];

    const int bn = blockIdx.x;   // 0..23  (N tiles)
    const int bm = blockIdx.y;   // 0..63  (M tiles)
    const int tid = threadIdx.x;
    const int tx = tid & 15;     // 16 col threads
    const int ty = tid >> 4;     // 16 row threads

    float acc[8][8];
#pragma unroll
    for (int i = 0; i < 8; i++)
#pragma unroll
        for (int j = 0; j < 8; j++) acc[i][j] = 0.0f;

    const int lr = tid >> 1;          // 0..127 row within tile
    const int lc = (tid & 1) * 4;     // 0 or 4 (k quad)
    const float* Ablk = x   + (size_t)(bm * 128) * kIN;
    const float* Bblk = Wih + (size_t)(bn * 128) * kIN;

    for (int k0 = 0; k0 < kIN; k0 += 8) {
        float4 a = *(const float4*)(Ablk + (size_t)lr * kIN + k0 + lc);
        float4 b = *(const float4*)(Bblk + (size_t)lr * kIN + k0 + lc);
        As[lc + 0][lr] = a.x; As[lc + 1][lr] = a.y; As[lc + 2][lr] = a.z; As[lc + 3][lr] = a.w;
        Bs[lc + 0][lr] = b.x; Bs[lc + 1][lr] = b.y; Bs[lc + 2][lr] = b.z; Bs[lc + 3][lr] = b.w;
        __syncthreads();
#pragma unroll
        for (int k = 0; k < 8; k++) {
            float ar[8], br[8];
#pragma unroll
            for (int i = 0; i < 8; i++) ar[i] = As[k][ty * 8 + i];
#pragma unroll
            for (int j = 0; j < 8; j++) br[j] = Bs[k][tx * 8 + j];
#pragma unroll
            for (int i = 0; i < 8; i++)
#pragma unroll
                for (int j = 0; j < 8; j++) acc[i][j] += ar[i] * br[j];
        }
        __syncthreads();
    }

    const int n0 = bn * 128 + tx * 8;
    float bv[8];
#pragma unroll
    for (int j = 0; j < 8; j++) bv[j] = bih[n0 + j];

#pragma unroll
    for (int i = 0; i < 8; i++) {
        int m = bm * 128 + ty * 8 + i;
        int w = m & 255;
        int b = m >> 8;
        float* orow = g_gi + ((size_t)w * kB + b) * kG + n0;
#pragma unroll
        for (int j = 0; j < 8; j++) orow[j] = acc[i][j] + bv[j];
    }
}

// ==================================================================================
// Kernel 2: persistent recurrence. 132 blocks: [0,128) GEMM blocks, [128,132) heads.
// ==================================================================================

// One GRU step for 8 h-columns owned by this block.
__device__ __forceinline__ void gemm_step(int t, int blk, const float* __restrict__ Whh,
                                          const float* __restrict__ bhh)
{
    __shared__ float hs[128][33];
    __shared__ float ws[24][128];

    const int tid = threadIdx.x;
    const int b   = tid & 31;
    const int jl  = tid >> 5;         // warp id = local h-column
    const int j0  = blk * 8;

    const float* hprev = g_hbuf[t & 1];
    float*       hnew  = g_hbuf[(t + 1) & 1];

    float ar = 0.0f, az = 0.0f, an = 0.0f;

    for (int kb = 0; kb < kH; kb += 128) {
#pragma unroll
        for (int i = 0; i < 16; i++) {
            int idx = i * 256 + tid;
            int bl = idx >> 7, kk = idx & 127;
            hs[kk][bl] = hprev[bl * kH + kb + kk];
        }
#pragma unroll
        for (int i = 0; i < 12; i++) {
            int idx = i * 256 + tid;
            int ri = idx >> 7, kk = idx & 127;
            int row = (ri >> 3) * kH + j0 + (ri & 7);
            ws[ri][kk] = Whh[(size_t)row * kH + kb + kk];
        }
        __syncthreads();
        const float* wr = ws[jl];
        const float* wz = ws[8 + jl];
        const float* wn = ws[16 + jl];
#pragma unroll
        for (int k = 0; k < 128; k++) {
            float hv = hs[k][b];
            ar += hv * wr[k];
            az += hv * wz[k];
            an += hv * wn[k];
        }
        __syncthreads();
    }

    const int j = j0 + jl;
    ar += bhh[j];
    az += bhh[kH + j];
    an += bhh[2 * kH + j];

    const float* git = g_gi + (size_t)t * (kB * kG) + b * kG;
    float r  = sigmoidf_(git[j] + ar);
    float zg = sigmoidf_(git[kH + j] + az);
    float n  = tanhf(git[2 * kH + j] + r * an);
    hnew[b * kH + j] = (1.0f - zg) * n + zg * hprev[b * kH + j];
}

// Head pipeline for output timestep s (needs h_s and z_{s-1}; produces z_s, mu_s, lv_s).
__device__ __forceinline__ void head_step(int s, int hb,
    const float* __restrict__ Wd,   const float* __restrict__ bd,
    const float* __restrict__ Wmu,  const float* __restrict__ bmu,
    const float* __restrict__ Wsig, const float* __restrict__ bsig,
    const float* __restrict__ u,    const float* __restrict__ Wpnf,
    const float* __restrict__ bpnf, const float* __restrict__ noise,
    float* __restrict__ out, int out_size)
{
    const int tid = threadIdx.x;
    const float* hcur = g_hbuf[(s + 1) & 1];
    const int d0 = hb * 25;
    const bool full_out = (out_size >= 3 * OUT_CHUNK);

    // ---- phase 1: dense_out = [z_{s-1} | h_s] @ Wd^T + bd  (this block: 25 cols)
    for (int oi = tid; oi < 25 * 32; oi += 256) {
        int d = d0 + (oi >> 5);
        int b = oi & 31;
        const float* wrow = Wd + (size_t)d * kDH;
        const float* zr = g_zbuf + b * kZ;
        const float* hr = hcur + b * kH;
        float acc = bd[d];
#pragma unroll 4
        for (int i = 0; i < kZ; i++) acc += zr[i] * wrow[i];
#pragma unroll 4
        for (int i = 0; i < kH; i++) acc += hr[i] * wrow[kZ + i];
        g_dense[b * kZ + d] = acc;
    }
    dev_barrier(&g_bar_head, 4);

    // ---- phase 2: mu, lv, zpre = mu + exp(0.5 lv) * eps
    for (int oi = tid; oi < 25 * 32; oi += 256) {
        int k = d0 + (oi >> 5);
        int b = oi & 31;
        const float* dr = g_dense + b * kZ;
        const float* wm = Wmu  + (size_t)k * kZ;
        const float* wsg = Wsig + (size_t)k * kZ;
        float am = bmu[k], as = bsig[k];
#pragma unroll 4
        for (int i = 0; i < kZ; i++) { float dv = dr[i]; am += dv * wm[i]; as += dv * wsg[i]; }
        float lv = softplusf_(as);
        float eps = noise[((size_t)s * kB + b) * kZ + k];
        float zp = am + expf(0.5f * lv) * eps;
        g_zpre[b * kZ + k] = zp;
        size_t o = (size_t)b * (kW * kZ) + (size_t)s * kZ + k;
        if (full_out) {
            out[OUT_CHUNK + o]     = am;   // mu
            out[2 * OUT_CHUNK + o] = lv;   // logvar
        }
    }
    dev_barrier(&g_bar_head, 4);

    // ---- phase 3: planar flow  z = zpre + u * tanh(zpre @ Wpnf^T + bpnf)
    const float u0 = u[0];
    for (int oi = tid; oi < 25 * 32; oi += 256) {
        int k = d0 + (oi >> 5);
        int b = oi & 31;
        const float* zr = g_zpre + b * kZ;
        const float* wp = Wpnf + (size_t)k * kZ;
        float acc = bpnf[k];
#pragma unroll 4
        for (int i = 0; i < kZ; i++) acc += zr[i] * wp[i];
        float zn = zr[k] + u0 * tanhf(acc);
        size_t o = (size_t)b * (kW * kZ) + (size_t)s * kZ + k;
        out[o] = zn;
        g_zbuf[b * kZ + k] = zn;
    }
}

__global__ void __launch_bounds__(256, 1) recurrence_kernel(
    const float* __restrict__ Whh,  const float* __restrict__ bhh,
    const float* __restrict__ Wd,   const float* __restrict__ bd,
    const float* __restrict__ Wmu,  const float* __restrict__ bmu,
    const float* __restrict__ Wsig, const float* __restrict__ bsig,
    const float* __restrict__ u,    const float* __restrict__ Wpnf,
    const float* __restrict__ bpnf, const float* __restrict__ noise,
    float* __restrict__ out, int out_size)
{
    const int tid = threadIdx.x;
    const int blk = blockIdx.x;
    const bool is_gemm = (blk < 128);

    // init state for this launch (device globals persist across graph replays)
    if (is_gemm) {
        int b = tid & 31, jl = tid >> 5;
        g_hbuf[0][b * kH + blk * 8 + jl] = 0.0f;
    } else {
        int hb = blk - 128;
        for (int i = tid; i < 800; i += 256) g_zbuf[hb * 800 + i] = 0.0f;
    }
    dev_barrier(&g_bar_all, 132);

    for (int t = 0; t < kW; t++) {
        if (is_gemm) {
            gemm_step(t, blk, Whh, bhh);
        } else if (t >= 1) {
            head_step(t - 1, blk - 128, Wd, bd, Wmu, bmu, Wsig, bsig,
                      u, Wpnf, bpnf, noise, out, out_size);
        }
        dev_barrier(&g_bar_all, 132);
    }
    if (!is_gemm) {
        head_step(kW - 1, blk - 128, Wd, bd, Wmu, bmu, Wsig, bsig,
                  u, Wpnf, bpnf, noise, out, out_size);
    }
}

// ==================================================================================
extern "C" void kernel_launch(void* const* d_in, const int* in_sizes, int n_in,
                              void* d_out, int out_size)
{
    const float* x    = (const float*)d_in[0];
    const float* Wih  = (const float*)d_in[1];
    const float* Whh  = (const float*)d_in[2];
    const float* bih  = (const float*)d_in[3];
    const float* bhh  = (const float*)d_in[4];
    const float* Wd   = (const float*)d_in[5];
    const float* bd   = (const float*)d_in[6];
    const float* Wmu  = (const float*)d_in[7];
    const float* bmu  = (const float*)d_in[8];
    const float* Wsig = (const float*)d_in[9];
    const float* bsig = (const float*)d_in[10];
    const float* u    = (const float*)d_in[11];
    const float* Wpnf = (const float*)d_in[12];
    const float* bpnf = (const float*)d_in[13];
    const float* noise= (const float*)d_in[14];

    dim3 grid1(24, 64);                       // N tiles x M tiles
    gemm_gi_kernel<<<grid1, 256>>>(x, Wih, bih);

    recurrence_kernel<<<132, 256>>>(Whh, bhh, Wd, bd, Wmu, bmu, Wsig, bsig,
                                    u, Wpnf, bpnf, noise, (float*)d_out, out_size);
}

// round 2
// speedup vs baseline: 11.0879x; 11.0879x over previous
#include <cuda_runtime.h>
#include <math.h>

// Problem dims
#define kB   32
#define kW   256
#define kIN  4096
#define kH   1024
#define kZ   100
#define kG   3072          // 3*kH
#define kDH  1124          // kZ + kH
#define OUT_CHUNK 819200   // kB*kW*kZ

#define NGEMM 128
#define NHEAD 8
#define NBLK  (NGEMM + NHEAD)

// -------------------- device scratch --------------------
__device__ float g_gi[kW * kB * kG];        // [w][b][g] precomputed input gates
__device__ float g_hbuf[2][kB * kH];        // [b][h]
__device__ float g_zbuf[kZ * kB];           // [k][b]  (feat-major for coalesced stores)
__device__ float g_dense[kZ * kB];          // [d][b]
__device__ float g_zpre[kZ * kB];           // [k][b]
__device__ unsigned long long g_bar_all = 0ULL;
__device__ unsigned long long g_bar_head = 0ULL;

// Monotonic-counter grid barrier (self-consistent across graph replays).
__device__ __forceinline__ void dev_barrier(unsigned long long* ctr, unsigned G)
{
    __syncthreads();
    if (threadIdx.x == 0) {
        __threadfence();
        unsigned long long old = atomicAdd(ctr, 1ULL);
        unsigned long long tgt = old - (old % (unsigned long long)G) + (unsigned long long)G;
        volatile unsigned long long* v = (volatile unsigned long long*)ctr;
        while (*v < tgt) { }
        __threadfence();
    }
    __syncthreads();
}

__device__ __forceinline__ float sigmoidf_(float x) { return 1.0f / (1.0f + expf(-x)); }
__device__ __forceinline__ float softplusf_(float x)
{
    return fmaxf(x, 0.0f) + log1pf(expf(-fabsf(x)));
}

// ==================================================================================
// Kernel 1: gi[w][b][g] = x @ W_ih^T + b_ih   (fp32 SGEMM, 128x128x8, 8x8/thread)
// ==================================================================================
__global__ void __launch_bounds__(256) gemm_gi_kernel(
    const float* __restrict__ x, const float* __restrict__ Wih,
    const float* __restrict__ bih)
{
    __shared__ float As[8][132];
    __shared__ float Bs[8][132];

    const int bn = blockIdx.x;
    const int bm = blockIdx.y;
    const int tid = threadIdx.x;
    const int tx = tid & 15;
    const int ty = tid >> 4;

    float acc[8][8];
#pragma unroll
    for (int i = 0; i < 8; i++)
#pragma unroll
        for (int j = 0; j < 8; j++) acc[i][j] = 0.0f;

    const int lr = tid >> 1;
    const int lc = (tid & 1) * 4;
    const float* Ablk = x   + (size_t)(bm * 128) * kIN;
    const float* Bblk = Wih + (size_t)(bn * 128) * kIN;

    for (int k0 = 0; k0 < kIN; k0 += 8) {
        float4 a = *(const float4*)(Ablk + (size_t)lr * kIN + k0 + lc);
        float4 b = *(const float4*)(Bblk + (size_t)lr * kIN + k0 + lc);
        As[lc + 0][lr] = a.x; As[lc + 1][lr] = a.y; As[lc + 2][lr] = a.z; As[lc + 3][lr] = a.w;
        Bs[lc + 0][lr] = b.x; Bs[lc + 1][lr] = b.y; Bs[lc + 2][lr] = b.z; Bs[lc + 3][lr] = b.w;
        __syncthreads();
#pragma unroll
        for (int k = 0; k < 8; k++) {
            float ar[8], br[8];
#pragma unroll
            for (int i = 0; i < 8; i++) ar[i] = As[k][ty * 8 + i];
#pragma unroll
            for (int j = 0; j < 8; j++) br[j] = Bs[k][tx * 8 + j];
#pragma unroll
            for (int i = 0; i < 8; i++)
#pragma unroll
                for (int j = 0; j < 8; j++) acc[i][j] += ar[i] * br[j];
        }
        __syncthreads();
    }

    const int n0 = bn * 128 + tx * 8;
    float bv[8];
#pragma unroll
    for (int j = 0; j < 8; j++) bv[j] = bih[n0 + j];

#pragma unroll
    for (int i = 0; i < 8; i++) {
        int m = bm * 128 + ty * 8 + i;
        int w = m & 255;
        int b = m >> 8;
        float* orow = g_gi + ((size_t)w * kB + b) * kG + n0;
#pragma unroll
        for (int j = 0; j < 8; j++) orow[j] = acc[i][j] + bv[j];
    }
}

// ==================================================================================
// Kernel 2: persistent recurrence. 136 blocks: [0,128) GRU-GEMM, [128,136) heads.
// Shared buffer union: gemm needs 128*33 + 24*128 floats; heads need 32*132 floats.
// ==================================================================================
#define SBUF_FLOATS (128*33 + 24*128)

__device__ __forceinline__ void gemm_step(int t, int blk, float* sbuf,
                                          const float* __restrict__ Whh,
                                          const float* __restrict__ bhh)
{
    float (*hs)[33]  = (float(*)[33])sbuf;
    float (*ws)[128] = (float(*)[128])(sbuf + 128 * 33);

    const int tid = threadIdx.x;
    const int b   = tid & 31;
    const int jl  = tid >> 5;
    const int j0  = blk * 8;

    const float* hprev = g_hbuf[t & 1];
    float*       hnew  = g_hbuf[(t + 1) & 1];

    float ar = 0.0f, az = 0.0f, an = 0.0f;

    for (int kb = 0; kb < kH; kb += 128) {
#pragma unroll
        for (int i = 0; i < 16; i++) {
            int idx = i * 256 + tid;
            int bl = idx >> 7, kk = idx & 127;
            hs[kk][bl] = __ldcg(&hprev[bl * kH + kb + kk]);
        }
#pragma unroll
        for (int i = 0; i < 12; i++) {
            int idx = i * 256 + tid;
            int ri = idx >> 7, kk = idx & 127;
            int row = (ri >> 3) * kH + j0 + (ri & 7);
            ws[ri][kk] = Whh[(size_t)row * kH + kb + kk];
        }
        __syncthreads();
        const float* wr = ws[jl];
        const float* wz = ws[8 + jl];
        const float* wn = ws[16 + jl];
#pragma unroll
        for (int k = 0; k < 128; k++) {
            float hv = hs[k][b];
            ar += hv * wr[k];
            az += hv * wz[k];
            an += hv * wn[k];
        }
        __syncthreads();
    }

    // stage this block's gi tile [32b][3 gates][8 j] into smem (semi-coalesced)
    float* gs = sbuf;  // reuse (synced above)
    const float* git = g_gi + (size_t)t * (kB * kG);
#pragma unroll
    for (int q = 0; q < 3; q++) {
        int v = q * 256 + tid;          // 0..767
        int bb = v / 24, r = v % 24;
        int gate = r >> 3, jj = r & 7;
        gs[bb * 24 + r] = git[(size_t)bb * kG + gate * kH + j0 + jj];
    }
    __syncthreads();

    const int j = j0 + jl;
    ar += bhh[j];
    az += bhh[kH + j];
    an += bhh[2 * kH + j];

    float gr = gs[b * 24 + jl];
    float gz = gs[b * 24 + 8 + jl];
    float gn = gs[b * 24 + 16 + jl];
    float hold = __ldcg(&hprev[b * kH + j]);
    float r  = sigmoidf_(gr + ar);
    float zg = sigmoidf_(gz + az);
    float n  = tanhf(gn + r * an);
    __stcg(&hnew[b * kH + j], (1.0f - zg) * n + zg * hold);
    __syncthreads();
}

__device__ __forceinline__ void head_step(int s, int hb, float* sbuf,
    const float* __restrict__ Wd,   const float* __restrict__ bd,
    const float* __restrict__ Wmu,  const float* __restrict__ bmu,
    const float* __restrict__ Wsig, const float* __restrict__ bsig,
    const float* __restrict__ u,    const float* __restrict__ Wpnf,
    const float* __restrict__ bpnf, const float* __restrict__ noise,
    float* __restrict__ out, int out_size)
{
    const int tid = threadIdx.x;
    const int b   = tid & 31;
    const int wid = tid >> 5;
    const int cnt = (hb < 4) ? 13 : 12;
    const int d0  = (hb < 4) ? hb * 13 : 52 + (hb - 4) * 12;
    float* bufA = sbuf;                 // [32][132]
    const float* hcur = g_hbuf[(s + 1) & 1];
    const bool full_out = (out_size >= 3 * OUT_CHUNK);

    // -------- phase 1: dense[d][b] = bd[d] + z.Wd_z + h.Wd_h ----------
    const int dA = wid;
    const int dB = wid + 8;
    const bool vB = (dB < cnt);
    const float* wrA = Wd + (size_t)(d0 + dA) * kDH;
    const float* wrB = Wd + (size_t)(d0 + (vB ? dB : dA)) * kDH;
    float acc0 = bd[d0 + dA];
    float acc1 = vB ? bd[d0 + dB] : 0.0f;

    // stage z (k-major global -> [b][k] smem)
    for (int i = tid; i < kZ * kB; i += 256) {
        int k = i >> 5, bb = i & 31;
        bufA[bb * 132 + k] = __ldcg(&g_zbuf[i]);
    }
    __syncthreads();
#pragma unroll
    for (int i = 0; i < kZ; i += 4) {
        float4 h4 = *(const float4*)&bufA[b * 132 + i];
        float4 wa = *(const float4*)&wrA[i];
        float4 wb = *(const float4*)&wrB[i];
        acc0 += h4.x * wa.x + h4.y * wa.y + h4.z * wa.z + h4.w * wa.w;
        acc1 += h4.x * wb.x + h4.y * wb.y + h4.z * wb.z + h4.w * wb.w;
    }
    __syncthreads();

    for (int kb = 0; kb < kH; kb += 128) {
#pragma unroll
        for (int q = 0; q < 4; q++) {
            int idx4 = (q * 256 + tid) * 4;
            int bb = idx4 >> 7, kk = idx4 & 127;
            *(float4*)&bufA[bb * 132 + kk] =
                __ldcg((const float4*)&hcur[bb * kH + kb + kk]);
        }
        __syncthreads();
        const float* wA = wrA + kZ + kb;
        const float* wB = wrB + kZ + kb;
#pragma unroll 8
        for (int k = 0; k < 128; k += 4) {
            float4 h4 = *(const float4*)&bufA[b * 132 + k];
            float4 wa = *(const float4*)&wA[k];
            float4 wb = *(const float4*)&wB[k];
            acc0 += h4.x * wa.x + h4.y * wa.y + h4.z * wa.z + h4.w * wa.w;
            acc1 += h4.x * wb.x + h4.y * wb.y + h4.z * wb.z + h4.w * wb.w;
        }
        __syncthreads();
    }
    __stcg(&g_dense[(d0 + dA) * kB + b], acc0);
    if (vB) __stcg(&g_dense[(d0 + dB) * kB + b], acc1);
    dev_barrier(&g_bar_head, NHEAD);

    // -------- phase 2: mu, lv, zpre ----------
    for (int i = tid; i < kZ * kB; i += 256) {
        int d = i >> 5, bb = i & 31;
        bufA[bb * 132 + d] = __ldcg(&g_dense[i]);
    }
    __syncthreads();
#pragma unroll
    for (int pass = 0; pass < 2; pass++) {
        int kl = wid + pass * 8;
        if (kl < cnt) {
            int k = d0 + kl;
            const float* wm  = Wmu  + (size_t)k * kZ;
            const float* wsg = Wsig + (size_t)k * kZ;
            float am = bmu[k], as = bsig[k];
#pragma unroll
            for (int i = 0; i < kZ; i += 4) {
                float4 d4 = *(const float4*)&bufA[b * 132 + i];
                float4 m4 = *(const float4*)&wm[i];
                float4 s4 = *(const float4*)&wsg[i];
                am += d4.x * m4.x + d4.y * m4.y + d4.z * m4.z + d4.w * m4.w;
                as += d4.x * s4.x + d4.y * s4.y + d4.z * s4.z + d4.w * s4.w;
            }
            float lv  = softplusf_(as);
            float eps = noise[((size_t)s * kB + b) * kZ + k];
            float zp  = am + expf(0.5f * lv) * eps;
            __stcg(&g_zpre[k * kB + b], zp);
            if (full_out) {
                size_t o = (size_t)b * (kW * kZ) + (size_t)s * kZ + k;
                out[OUT_CHUNK + o]     = am;
                out[2 * OUT_CHUNK + o] = lv;
            }
        }
    }
    dev_barrier(&g_bar_head, NHEAD);

    // -------- phase 3: planar flow ----------
    for (int i = tid; i < kZ * kB; i += 256) {
        int k = i >> 5, bb = i & 31;
        bufA[bb * 132 + k] = __ldcg(&g_zpre[i]);
    }
    __syncthreads();
    const float u0 = u[0];
#pragma unroll
    for (int pass = 0; pass < 2; pass++) {
        int kl = wid + pass * 8;
        if (kl < cnt) {
            int k = d0 + kl;
            const float* wp = Wpnf + (size_t)k * kZ;
            float acc = bpnf[k];
#pragma unroll
            for (int i = 0; i < kZ; i += 4) {
                float4 z4 = *(const float4*)&bufA[b * 132 + i];
                float4 p4 = *(const float4*)&wp[i];
                acc += z4.x * p4.x + z4.y * p4.y + z4.z * p4.z + z4.w * p4.w;
            }
            float zn = bufA[b * 132 + k] + u0 * tanhf(acc);
            size_t o = (size_t)b * (kW * kZ) + (size_t)s * kZ + k;
            out[o] = zn;
            __stcg(&g_zbuf[k * kB + b], zn);
        }
    }
    __syncthreads();
}

__global__ void __launch_bounds__(256, 1) recurrence_kernel(
    const float* __restrict__ Whh,  const float* __restrict__ bhh,
    const float* __restrict__ Wd,   const float* __restrict__ bd,
    const float* __restrict__ Wmu,  const float* __restrict__ bmu,
    const float* __restrict__ Wsig, const float* __restrict__ bsig,
    const float* __restrict__ u,    const float* __restrict__ Wpnf,
    const float* __restrict__ bpnf, const float* __restrict__ noise,
    float* __restrict__ out, int out_size)
{
    __shared__ float sbuf[SBUF_FLOATS];
    const int tid = threadIdx.x;
    const int blk = blockIdx.x;
    const bool is_gemm = (blk < NGEMM);

    if (is_gemm) {
        int b = tid & 31, jl = tid >> 5;
        __stcg(&g_hbuf[0][b * kH + blk * 8 + jl], 0.0f);
    } else {
        int hb = blk - NGEMM;
        for (int i = tid; i < 400; i += 256) __stcg(&g_zbuf[hb * 400 + i], 0.0f);
    }
    dev_barrier(&g_bar_all, NBLK);

    for (int t = 0; t < kW; t++) {
        if (is_gemm) {
            gemm_step(t, blk, sbuf, Whh, bhh);
        } else if (t >= 1) {
            head_step(t - 1, blk - NGEMM, sbuf, Wd, bd, Wmu, bmu, Wsig, bsig,
                      u, Wpnf, bpnf, noise, out, out_size);
        }
        dev_barrier(&g_bar_all, NBLK);
    }
    if (!is_gemm) {
        head_step(kW - 1, blk - NGEMM, sbuf, Wd, bd, Wmu, bmu, Wsig, bsig,
                  u, Wpnf, bpnf, noise, out, out_size);
    }
}

// ==================================================================================
extern "C" void kernel_launch(void* const* d_in, const int* in_sizes, int n_in,
                              void* d_out, int out_size)
{
    const float* x    = (const float*)d_in[0];
    const float* Wih  = (const float*)d_in[1];
    const float* Whh  = (const float*)d_in[2];
    const float* bih  = (const float*)d_in[3];
    const float* bhh  = (const float*)d_in[4];
    const float* Wd   = (const float*)d_in[5];
    const float* bd   = (const float*)d_in[6];
    const float* Wmu  = (const float*)d_in[7];
    const float* bmu  = (const float*)d_in[8];
    const float* Wsig = (const float*)d_in[9];
    const float* bsig = (const float*)d_in[10];
    const float* u    = (const float*)d_in[11];
    const float* Wpnf = (const float*)d_in[12];
    const float* bpnf = (const float*)d_in[13];
    const float* noise= (const float*)d_in[14];

    dim3 grid1(24, 64);
    gemm_gi_kernel<<<grid1, 256>>>(x, Wih, bih);

    recurrence_kernel<<<NBLK, 256>>>(Whh, bhh, Wd, bd, Wmu, bmu, Wsig, bsig,
                                     u, Wpnf, bpnf, noise, (float*)d_out, out_size);
}

// round 5
// speedup vs baseline: 15.9311x; 1.4368x over previous
#include <cuda_runtime.h>
#include <cuda_bf16.h>
#include <math.h>
#include <stdint.h>

// Problem dims
#define kB   32
#define kW   256
#define kIN  4096
#define kH   1024
#define kZ   100
#define kG   3072
#define kDH  1124
#define OUT_CHUNK 819200

#define NGEMM 128
#define NHEAD 8
#define NBLK  (NGEMM + NHEAD)

// big GEMM dims
#define GM 8192
#define GN 3072
#define GK 4096
#define KS 64
#define NST (GK / KS)                 // 64 stages
#define STAGE 65536                   // Ah16K | Al16K | Bh16K | Bl16K
#define GEMM_SMEM (3 * STAGE)         // 196608

// -------------------- device scratch --------------------
__device__ float g_gi[kW * kB * kG];                 // [w][b][g]
__device__ __nv_bfloat16 g_Ah[(size_t)GM * GK];
__device__ __nv_bfloat16 g_Al[(size_t)GM * GK];
__device__ __nv_bfloat16 g_Bh[(size_t)GN * GK];
__device__ __nv_bfloat16 g_Bl[(size_t)GN * GK];
__device__ float g_hbuf[2][kB * kH];
__device__ float g_zbuf[kZ * kB];
__device__ float g_dense[kZ * kB];
__device__ float g_zpre[kZ * kB];
__device__ unsigned long long g_bar_all = 0ULL;
__device__ unsigned long long g_bar_head = 0ULL;

// -------------------- PTX helpers (sm_80-baseline only) --------------------
__device__ __forceinline__ uint32_t smem_u32(const void* p) {
    uint32_t a;
    asm("{ .reg .u64 t; cvta.to.shared.u64 t, %1; cvt.u32.u64 %0, t; }" : "=r"(a) : "l"(p));
    return a;
}
#define CP_ASYNC16(dst, src) \
    asm volatile("cp.async.cg.shared.global [%0], [%1], 16;" :: "r"(dst), "l"(src))
#define CP_COMMIT() asm volatile("cp.async.commit_group;" ::: "memory")
#define CP_WAIT2()  asm volatile("cp.async.wait_group 2;" ::: "memory")

#define LDSM_X4(r0, r1, r2, r3, a) \
    asm volatile("ldmatrix.sync.aligned.m8n8.x4.shared.b16 {%0,%1,%2,%3}, [%4];" \
        : "=r"(r0), "=r"(r1), "=r"(r2), "=r"(r3) : "r"(a))

#define MMA16816(d, a, b) \
    asm volatile("mma.sync.aligned.m16n8k16.row.col.f32.bf16.bf16.f32 " \
        "{%0,%1,%2,%3}, {%4,%5,%6,%7}, {%8,%9}, {%0,%1,%2,%3};" \
        : "+f"((d)[0]), "+f"((d)[1]), "+f"((d)[2]), "+f"((d)[3]) \
        : "r"((a)[0]), "r"((a)[1]), "r"((a)[2]), "r"((a)[3]), "r"((b)[0]), "r"((b)[1]))

#define SW128(o) ((o) ^ (((o) >> 3) & 0x70))

// -------------------- misc math --------------------
__device__ __forceinline__ float sigmoidf_(float x) { return 1.0f / (1.0f + expf(-x)); }
__device__ __forceinline__ float softplusf_(float x)
{
    return fmaxf(x, 0.0f) + log1pf(expf(-fabsf(x)));
}

__device__ __forceinline__ void dev_barrier(unsigned long long* ctr, unsigned G)
{
    __syncthreads();
    if (threadIdx.x == 0) {
        __threadfence();
        unsigned long long old = atomicAdd(ctr, 1ULL);
        unsigned long long tgt = old - (old % (unsigned long long)G) + (unsigned long long)G;
        volatile unsigned long long* v = (volatile unsigned long long*)ctr;
        while (*v < tgt) { }
        __threadfence();
    }
    __syncthreads();
}

// ==================================================================================
// Kernel 0: split fp32 -> (hi, lo) bf16 pairs for x and W_ih
// ==================================================================================
__global__ void __launch_bounds__(256) convert_split(
    const float* __restrict__ x, const float* __restrict__ Wih)
{
    int row = blockIdx.x;
    const float* src;
    __nv_bfloat16 *dh, *dl;
    if (row < GM) {
        src = x + (size_t)row * GK;
        dh = g_Ah + (size_t)row * GK;
        dl = g_Al + (size_t)row * GK;
    } else {
        int r = row - GM;
        src = Wih + (size_t)r * GK;
        dh = g_Bh + (size_t)r * GK;
        dl = g_Bl + (size_t)r * GK;
    }
    for (int i4 = threadIdx.x; i4 < GK / 4; i4 += 256) {
        float4 v = ((const float4*)src)[i4];
        __nv_bfloat16 h0 = __float2bfloat16_rn(v.x);
        __nv_bfloat16 h1 = __float2bfloat16_rn(v.y);
        __nv_bfloat16 h2 = __float2bfloat16_rn(v.z);
        __nv_bfloat16 h3 = __float2bfloat16_rn(v.w);
        __nv_bfloat16 l0 = __float2bfloat16_rn(v.x - __bfloat162float(h0));
        __nv_bfloat16 l1 = __float2bfloat16_rn(v.y - __bfloat162float(h1));
        __nv_bfloat16 l2 = __float2bfloat16_rn(v.z - __bfloat162float(h2));
        __nv_bfloat16 l3 = __float2bfloat16_rn(v.w - __bfloat162float(h3));
        ((__nv_bfloat162*)dh)[i4 * 2 + 0] = __halves2bfloat162(h0, h1);
        ((__nv_bfloat162*)dh)[i4 * 2 + 1] = __halves2bfloat162(h2, h3);
        ((__nv_bfloat162*)dl)[i4 * 2 + 0] = __halves2bfloat162(l0, l1);
        ((__nv_bfloat162*)dl)[i4 * 2 + 1] = __halves2bfloat162(l2, l3);
    }
}

// ==================================================================================
// Kernel 1: HMMA bf16-split GEMM: gi = x @ Wih^T + bih
// 128x128 tile, 8 warps (2x4), warp tile 64x32, 3-stage cp.async pipeline.
// ==================================================================================
__global__ void __launch_bounds__(256, 1) gemm_gi_hmma(const float* __restrict__ bih)
{
    extern __shared__ char smem[];
    const uint32_t sb = smem_u32(smem);
    const int tid  = threadIdx.x;
    const int lane = tid & 31;
    const int wid  = tid >> 5;
    const int mw   = wid >> 2;            // 0..1 : m offset 64
    const int nw   = wid & 3;             // 0..3 : n offset 32
    const int m0   = blockIdx.y * 128;
    const int n0   = blockIdx.x * 128;

    float d[4][4][4];
#pragma unroll
    for (int i = 0; i < 4; i++)
#pragma unroll
        for (int j = 0; j < 4; j++)
#pragma unroll
            for (int c = 0; c < 4; c++) d[i][j][c] = 0.0f;

    // ---- stage loader: buf layout Ah|Al|Bh|Bl, 16KB each, SW128 rows of 128B ----
    const int lr = tid >> 3;              // 0..31 (row sub-index)
    const int lc = tid & 7;               // 0..7  (16B column)
    auto load_stage = [&](int s) {
        uint32_t base = sb + (s % 3) * STAGE;
        size_t k0 = (size_t)s * KS;
#pragma unroll
        for (int i = 0; i < 16; i++) {
            const int buf = i >> 2;                    // 0..3 (compile-time)
            const int r   = (i & 3) * 32 + lr;         // 0..127
            const __nv_bfloat16* g =
                (buf == 0) ? g_Ah : (buf == 1) ? g_Al : (buf == 2) ? g_Bh : g_Bl;
            const int row = ((buf < 2) ? m0 : n0) + r;
            const __nv_bfloat16* src = g + (size_t)row * GK + k0 + lc * 8;
            uint32_t dst = base + buf * 16384 + SW128(r * 128 + lc * 16);
            CP_ASYNC16(dst, src);
        }
    };

    load_stage(0); CP_COMMIT();
    load_stage(1); CP_COMMIT();
    load_stage(2); CP_COMMIT();

    // ldmatrix lane-address components
    const int rowA_off = (lane & 7) + ((lane >> 3) & 1) * 8;   // groups 0/1: +0/+8
    const int kA_extra = ((lane >> 4) & 1) * 16;               // groups 2/3: k+8
    const int rowB_off = (lane & 7) + ((lane >> 4) & 1) * 8;   // groups 0,1 / 2,3
    const int kB_extra = ((lane >> 3) & 1) * 16;               // groups 1,3: k+8

#pragma unroll 1
    for (int s = 0; s < NST; s++) {
        CP_WAIT2();
        __syncthreads();
        const uint32_t base = sb + (s % 3) * STAGE;

#pragma unroll
        for (int kk = 0; kk < 4; kk++) {
            const int kb = kk * 32;                     // byte offset of k16 chunk
            uint32_t ah[4][4], al[4][4], bh[4][2], bl[4][2];
#pragma unroll
            for (int mt = 0; mt < 4; mt++) {
                int row = mw * 64 + mt * 16 + rowA_off;
                uint32_t off = SW128(row * 128 + kb + kA_extra);
                LDSM_X4(ah[mt][0], ah[mt][1], ah[mt][2], ah[mt][3], base + off);
                LDSM_X4(al[mt][0], al[mt][1], al[mt][2], al[mt][3], base + 16384 + off);
            }
#pragma unroll
            for (int p = 0; p < 2; p++) {
                int row = nw * 32 + p * 16 + rowB_off;
                uint32_t off = SW128(row * 128 + kb + kB_extra);
                uint32_t t0, t1, t2, t3;
                LDSM_X4(t0, t1, t2, t3, base + 32768 + off);
                bh[2 * p][0] = t0; bh[2 * p][1] = t1;
                bh[2 * p + 1][0] = t2; bh[2 * p + 1][1] = t3;
                LDSM_X4(t0, t1, t2, t3, base + 49152 + off);
                bl[2 * p][0] = t0; bl[2 * p][1] = t1;
                bl[2 * p + 1][0] = t2; bl[2 * p + 1][1] = t3;
            }
#pragma unroll
            for (int mt = 0; mt < 4; mt++)
#pragma unroll
                for (int nt = 0; nt < 4; nt++) {
                    MMA16816(d[mt][nt], ah[mt], bh[nt]);
                    MMA16816(d[mt][nt], ah[mt], bl[nt]);
                    MMA16816(d[mt][nt], al[mt], bh[nt]);
                }
        }
        __syncthreads();
        if (s + 3 < NST) load_stage(s + 3);
        CP_COMMIT();
    }

    // ---- epilogue: add bias, scatter to g_gi[w][b][g] (m = b*256 + w) ----
#pragma unroll
    for (int nt = 0; nt < 4; nt++) {
        const int n = n0 + nw * 32 + nt * 8 + (lane & 3) * 2;
        const float2 bv = *(const float2*)(bih + n);
#pragma unroll
        for (int mt = 0; mt < 4; mt++) {
            int mrow = m0 + mw * 64 + mt * 16 + (lane >> 2);
            int b = mrow >> 8;
            int w = mrow & 255;
            float* dst1 = g_gi + ((size_t)w * kB + b) * kG + n;
            float* dst2 = dst1 + (size_t)8 * kB * kG;    // row mrow+8: same b, w+8
            float2 v1 = { d[mt][nt][0] + bv.x, d[mt][nt][1] + bv.y };
            float2 v2 = { d[mt][nt][2] + bv.x, d[mt][nt][3] + bv.y };
            *(float2*)dst1 = v1;
            *(float2*)dst2 = v2;
        }
    }
}

// ==================================================================================
// Kernel 2: persistent recurrence (unchanged from round 2 — known good, ~3ms)
// ==================================================================================
#define SBUF_FLOATS (128*33 + 24*128)

__device__ __forceinline__ void gemm_step(int t, int blk, float* sbuf,
                                          const float* __restrict__ Whh,
                                          const float* __restrict__ bhh)
{
    float (*hs)[33]  = (float(*)[33])sbuf;
    float (*ws)[128] = (float(*)[128])(sbuf + 128 * 33);

    const int tid = threadIdx.x;
    const int b   = tid & 31;
    const int jl  = tid >> 5;
    const int j0  = blk * 8;

    const float* hprev = g_hbuf[t & 1];
    float*       hnew  = g_hbuf[(t + 1) & 1];

    float ar = 0.0f, az = 0.0f, an = 0.0f;

    for (int kb = 0; kb < kH; kb += 128) {
#pragma unroll
        for (int i = 0; i < 16; i++) {
            int idx = i * 256 + tid;
            int bl = idx >> 7, kk = idx & 127;
            hs[kk][bl] = __ldcg(&hprev[bl * kH + kb + kk]);
        }
#pragma unroll
        for (int i = 0; i < 12; i++) {
            int idx = i * 256 + tid;
            int ri = idx >> 7, kk = idx & 127;
            int row = (ri >> 3) * kH + j0 + (ri & 7);
            ws[ri][kk] = Whh[(size_t)row * kH + kb + kk];
        }
        __syncthreads();
        const float* wr = ws[jl];
        const float* wz = ws[8 + jl];
        const float* wn = ws[16 + jl];
#pragma unroll
        for (int k = 0; k < 128; k++) {
            float hv = hs[k][b];
            ar += hv * wr[k];
            az += hv * wz[k];
            an += hv * wn[k];
        }
        __syncthreads();
    }

    float* gs = sbuf;
    const float* git = g_gi + (size_t)t * (kB * kG);
#pragma unroll
    for (int q = 0; q < 3; q++) {
        int v = q * 256 + tid;
        int bb = v / 24, r = v % 24;
        int gate = r >> 3, jj = r & 7;
        gs[bb * 24 + r] = git[(size_t)bb * kG + gate * kH + j0 + jj];
    }
    __syncthreads();

    const int j = j0 + jl;
    ar += bhh[j];
    az += bhh[kH + j];
    an += bhh[2 * kH + j];

    float gr = gs[b * 24 + jl];
    float gz = gs[b * 24 + 8 + jl];
    float gn = gs[b * 24 + 16 + jl];
    float hold = __ldcg(&hprev[b * kH + j]);
    float r  = sigmoidf_(gr + ar);
    float zg = sigmoidf_(gz + az);
    float n  = tanhf(gn + r * an);
    __stcg(&hnew[b * kH + j], (1.0f - zg) * n + zg * hold);
    __syncthreads();
}

__device__ __forceinline__ void head_step(int s, int hb, float* sbuf,
    const float* __restrict__ Wd,   const float* __restrict__ bd,
    const float* __restrict__ Wmu,  const float* __restrict__ bmu,
    const float* __restrict__ Wsig, const float* __restrict__ bsig,
    const float* __restrict__ u,    const float* __restrict__ Wpnf,
    const float* __restrict__ bpnf, const float* __restrict__ noise,
    float* __restrict__ out, int out_size)
{
    const int tid = threadIdx.x;
    const int b   = tid & 31;
    const int wid = tid >> 5;
    const int cnt = (hb < 4) ? 13 : 12;
    const int d0  = (hb < 4) ? hb * 13 : 52 + (hb - 4) * 12;
    float* bufA = sbuf;
    const float* hcur = g_hbuf[(s + 1) & 1];
    const bool full_out = (out_size >= 3 * OUT_CHUNK);

    const int dA = wid;
    const int dB = wid + 8;
    const bool vB = (dB < cnt);
    const float* wrA = Wd + (size_t)(d0 + dA) * kDH;
    const float* wrB = Wd + (size_t)(d0 + (vB ? dB : dA)) * kDH;
    float acc0 = bd[d0 + dA];
    float acc1 = vB ? bd[d0 + dB] : 0.0f;

    for (int i = tid; i < kZ * kB; i += 256) {
        int k = i >> 5, bb = i & 31;
        bufA[bb * 132 + k] = __ldcg(&g_zbuf[i]);
    }
    __syncthreads();
#pragma unroll
    for (int i = 0; i < kZ; i += 4) {
        float4 h4 = *(const float4*)&bufA[b * 132 + i];
        float4 wa = *(const float4*)&wrA[i];
        float4 wb = *(const float4*)&wrB[i];
        acc0 += h4.x * wa.x + h4.y * wa.y + h4.z * wa.z + h4.w * wa.w;
        acc1 += h4.x * wb.x + h4.y * wb.y + h4.z * wb.z + h4.w * wb.w;
    }
    __syncthreads();

    for (int kb = 0; kb < kH; kb += 128) {
#pragma unroll
        for (int q = 0; q < 4; q++) {
            int idx4 = (q * 256 + tid) * 4;
            int bb = idx4 >> 7, kk = idx4 & 127;
            *(float4*)&bufA[bb * 132 + kk] =
                __ldcg((const float4*)&hcur[bb * kH + kb + kk]);
        }
        __syncthreads();
        const float* wA = wrA + kZ + kb;
        const float* wB = wrB + kZ + kb;
#pragma unroll 8
        for (int k = 0; k < 128; k += 4) {
            float4 h4 = *(const float4*)&bufA[b * 132 + k];
            float4 wa = *(const float4*)&wA[k];
            float4 wb = *(const float4*)&wB[k];
            acc0 += h4.x * wa.x + h4.y * wa.y + h4.z * wa.z + h4.w * wa.w;
            acc1 += h4.x * wb.x + h4.y * wb.y + h4.z * wb.z + h4.w * wb.w;
        }
        __syncthreads();
    }
    __stcg(&g_dense[(d0 + dA) * kB + b], acc0);
    if (vB) __stcg(&g_dense[(d0 + dB) * kB + b], acc1);
    dev_barrier(&g_bar_head, NHEAD);

    for (int i = tid; i < kZ * kB; i += 256) {
        int d = i >> 5, bb = i & 31;
        bufA[bb * 132 + d] = __ldcg(&g_dense[i]);
    }
    __syncthreads();
#pragma unroll
    for (int pass = 0; pass < 2; pass++) {
        int kl = wid + pass * 8;
        if (kl < cnt) {
            int k = d0 + kl;
            const float* wm  = Wmu  + (size_t)k * kZ;
            const float* wsg = Wsig + (size_t)k * kZ;
            float am = bmu[k], as = bsig[k];
#pragma unroll
            for (int i = 0; i < kZ; i += 4) {
                float4 d4 = *(const float4*)&bufA[b * 132 + i];
                float4 m4 = *(const float4*)&wm[i];
                float4 s4 = *(const float4*)&wsg[i];
                am += d4.x * m4.x + d4.y * m4.y + d4.z * m4.z + d4.w * m4.w;
                as += d4.x * s4.x + d4.y * s4.y + d4.z * s4.z + d4.w * s4.w;
            }
            float lv  = softplusf_(as);
            float eps = noise[((size_t)s * kB + b) * kZ + k];
            float zp  = am + expf(0.5f * lv) * eps;
            __stcg(&g_zpre[k * kB + b], zp);
            if (full_out) {
                size_t o = (size_t)b * (kW * kZ) + (size_t)s * kZ + k;
                out[OUT_CHUNK + o]     = am;
                out[2 * OUT_CHUNK + o] = lv;
            }
        }
    }
    dev_barrier(&g_bar_head, NHEAD);

    for (int i = tid; i < kZ * kB; i += 256) {
        int k = i >> 5, bb = i & 31;
        bufA[bb * 132 + k] = __ldcg(&g_zpre[i]);
    }
    __syncthreads();
    const float u0 = u[0];
#pragma unroll
    for (int pass = 0; pass < 2; pass++) {
        int kl = wid + pass * 8;
        if (kl < cnt) {
            int k = d0 + kl;
            const float* wp = Wpnf + (size_t)k * kZ;
            float acc = bpnf[k];
#pragma unroll
            for (int i = 0; i < kZ; i += 4) {
                float4 z4 = *(const float4*)&bufA[b * 132 + i];
                float4 p4 = *(const float4*)&wp[i];
                acc += z4.x * p4.x + z4.y * p4.y + z4.z * p4.z + z4.w * p4.w;
            }
            float zn = bufA[b * 132 + k] + u0 * tanhf(acc);
            size_t o = (size_t)b * (kW * kZ) + (size_t)s * kZ + k;
            out[o] = zn;
            __stcg(&g_zbuf[k * kB + b], zn);
        }
    }
    __syncthreads();
}

__global__ void __launch_bounds__(256, 1) recurrence_kernel(
    const float* __restrict__ Whh,  const float* __restrict__ bhh,
    const float* __restrict__ Wd,   const float* __restrict__ bd,
    const float* __restrict__ Wmu,  const float* __restrict__ bmu,
    const float* __restrict__ Wsig, const float* __restrict__ bsig,
    const float* __restrict__ u,    const float* __restrict__ Wpnf,
    const float* __restrict__ bpnf, const float* __restrict__ noise,
    float* __restrict__ out, int out_size)
{
    __shared__ float sbuf[SBUF_FLOATS];
    const int tid = threadIdx.x;
    const int blk = blockIdx.x;
    const bool is_gemm = (blk < NGEMM);

    if (is_gemm) {
        int b = tid & 31, jl = tid >> 5;
        __stcg(&g_hbuf[0][b * kH + blk * 8 + jl], 0.0f);
    } else {
        int hb = blk - NGEMM;
        for (int i = tid; i < 400; i += 256) __stcg(&g_zbuf[hb * 400 + i], 0.0f);
    }
    dev_barrier(&g_bar_all, NBLK);

    for (int t = 0; t < kW; t++) {
        if (is_gemm) {
            gemm_step(t, blk, sbuf, Whh, bhh);
        } else if (t >= 1) {
            head_step(t - 1, blk - NGEMM, sbuf, Wd, bd, Wmu, bmu, Wsig, bsig,
                      u, Wpnf, bpnf, noise, out, out_size);
        }
        dev_barrier(&g_bar_all, NBLK);
    }
    if (!is_gemm) {
        head_step(kW - 1, blk - NGEMM, sbuf, Wd, bd, Wmu, bmu, Wsig, bsig,
                  u, Wpnf, bpnf, noise, out, out_size);
    }
}

// ==================================================================================
extern "C" void kernel_launch(void* const* d_in, const int* in_sizes, int n_in,
                              void* d_out, int out_size)
{
    const float* x    = (const float*)d_in[0];
    const float* Wih  = (const float*)d_in[1];
    const float* Whh  = (const float*)d_in[2];
    const float* bih  = (const float*)d_in[3];
    const float* bhh  = (const float*)d_in[4];
    const float* Wd   = (const float*)d_in[5];
    const float* bd   = (const float*)d_in[6];
    const float* Wmu  = (const float*)d_in[7];
    const float* bmu  = (const float*)d_in[8];
    const float* Wsig = (const float*)d_in[9];
    const float* bsig = (const float*)d_in[10];
    const float* u    = (const float*)d_in[11];
    const float* Wpnf = (const float*)d_in[12];
    const float* bpnf = (const float*)d_in[13];
    const float* noise= (const float*)d_in[14];

    convert_split<<<GM + GN, 256>>>(x, Wih);

    static int smem_set = 0;
    if (!smem_set) {
        cudaFuncSetAttribute(gemm_gi_hmma, cudaFuncAttributeMaxDynamicSharedMemorySize,
                             GEMM_SMEM);
        smem_set = 1;
    }
    dim3 grid_g(GN / 128, GM / 128);   // 24 x 64
    gemm_gi_hmma<<<grid_g, 256, GEMM_SMEM>>>(bih);

    recurrence_kernel<<<NBLK, 256>>>(Whh, bhh, Wd, bd, Wmu, bmu, Wsig, bsig,
                                     u, Wpnf, bpnf, noise, (float*)d_out, out_size);
}